// round 15
// baseline (speedup 1.0000x reference)
#include <cuda_runtime.h>
#include <cuda_bf16.h>
#include <cstdint>

#define TGT 2048
#define SRC 2048
#define BHN 16
#define DH  64
#define QK_SCALE 0.125f

#define STR 72    // QK smem stride (halfs): 144B rows, conflict-free ldmatrix
#define PSTR 40   // PV smem stride (halfs): 80B rows, conflict-free ldmatrix

// Deterministic per-row exp-sum partials: [h][t][sblock*2 + swarp]
__device__ float LSUM[(size_t)BHN * TGT * 32];

// ---------------------------------------------------------------------------
// Helpers
// ---------------------------------------------------------------------------
__device__ __forceinline__ uint32_t smem_to_u32(const void* p) {
    uint32_t a;
    asm("{ .reg .u64 t; cvta.to.shared.u64 t, %1; cvt.u32.u64 %0, t; }"
        : "=r"(a) : "l"(p));
    return a;
}

__device__ __forceinline__ void ldmx4(uint32_t* r, uint32_t a) {
    asm volatile("ldmatrix.sync.aligned.m8n8.x4.shared.b16 {%0,%1,%2,%3}, [%4];"
                 : "=r"(r[0]), "=r"(r[1]), "=r"(r[2]), "=r"(r[3]) : "r"(a));
}

__device__ __forceinline__ void mma_bf16(float* c, const uint32_t* a, const uint32_t* b) {
    asm volatile(
        "mma.sync.aligned.m16n8k16.row.col.f32.bf16.bf16.f32 "
        "{%0,%1,%2,%3}, {%4,%5,%6,%7}, {%8,%9}, {%0,%1,%2,%3};"
        : "+f"(c[0]), "+f"(c[1]), "+f"(c[2]), "+f"(c[3])
        : "r"(a[0]), "r"(a[1]), "r"(a[2]), "r"(a[3]), "r"(b[0]), "r"(b[1]));
}

__device__ __forceinline__ uint32_t pack_hi(float a, float b) {
    __nv_bfloat162 t = __floats2bfloat162_rn(a, b);
    return *reinterpret_cast<uint32_t*>(&t);
}
__device__ __forceinline__ float bf_hi(float x) {
    return __bfloat162float(__float2bfloat16_rn(x));
}
__device__ __forceinline__ uint32_t pack_lo(float a, float b) {
    __nv_bfloat162 t = __floats2bfloat162_rn(a - bf_hi(a), b - bf_hi(b));
    return *reinterpret_cast<uint32_t*>(&t);
}

// ---------------------------------------------------------------------------
// Kernel A: W[h,t,s] = mask ? 0 : exp((Q/8)·K), plus per-row partial sums.
// Block 256 thr, tile 128x128, LOOPS OVER 8 HEADS (blockIdx.z selects half).
// Mask bits for this thread's 64 epilogue elements are packed into one
// uint64 register once and reused across heads (7/8 mask traffic saved).
// Warps 4(t) x 2(s); warp tile 32x64 (1:4 ldm:MMA).
// exp without max-subtraction is safe: |logit| <~ 8 (unit-variance inputs).
// ---------------------------------------------------------------------------
#define QK_SMEM_BYTES (4 * 128 * STR * 2)   // Qhi, Qlo, Khi, Klo

__global__ __launch_bounds__(256, 2) void qk_tc_kernel(
    const float* __restrict__ Q, const float* __restrict__ K,
    const int* __restrict__ mask, float* __restrict__ W)
{
    extern __shared__ char smem[];
    __nv_bfloat16* sQh = reinterpret_cast<__nv_bfloat16*>(smem);
    __nv_bfloat16* sQl = sQh + 128 * STR;
    __nv_bfloat16* sKh = sQl + 128 * STR;
    __nv_bfloat16* sKl = sKh + 128 * STR;

    const int tid = threadIdx.x;
    const int lane = tid & 31, wid = tid >> 5;
    const int tb = blockIdx.y * 128;
    const int sb = blockIdx.x * 128;
    const int hbase = blockIdx.z * 8;
    const int wt = (wid & 3) * 32;
    const int ws = (wid >> 2) * 64;

    // Pack this thread's epilogue mask bits (h-invariant) once.
    uint64_t mb = 0;
#pragma unroll
    for (int mi = 0; mi < 2; ++mi) {
#pragma unroll
        for (int ni = 0; ni < 8; ++ni) {
            int t0 = tb + wt + mi * 16 + (lane >> 2);
            int s  = sb + ws + ni * 8 + (lane & 3) * 2;
            int2 m0 = *reinterpret_cast<const int2*>(mask + (size_t)t0 * SRC + s);
            int2 m1 = *reinterpret_cast<const int2*>(mask + (size_t)(t0 + 8) * SRC + s);
            int p = (mi * 8 + ni) * 4;
            mb |= (uint64_t)(m0.x ? 1u : 0u) << p;
            mb |= (uint64_t)(m0.y ? 1u : 0u) << (p + 1);
            mb |= (uint64_t)(m1.x ? 1u : 0u) << (p + 2);
            mb |= (uint64_t)(m1.y ? 1u : 0u) << (p + 3);
        }
    }

    const uint32_t bQh = smem_to_u32(sQh), bQl = smem_to_u32(sQl);
    const uint32_t bKh = smem_to_u32(sKh), bKl = smem_to_u32(sKl);

    const int a_row = (lane & 15);
    const int a_co8 = (lane >> 4) << 3;
    const int b_row = (lane & 7) + ((lane & 16) >> 1);
    const int b_co8 = (lane & 8);

#pragma unroll 1
    for (int hh = 0; hh < 8; ++hh) {
        const int h = hbase + hh;
        __syncthreads();   // prior iteration's ldmatrix reads complete

        // Convert Q (scaled) and K tiles to bf16 hi/lo.
#pragma unroll
        for (int k = 0; k < 8; ++k) {
            int i  = tid + k * 256;
            int r  = i >> 4;
            int c4 = (i & 15) << 2;
            int hidx = r * STR + c4;

            float4 q = *reinterpret_cast<const float4*>(
                Q + (size_t)(tb + r) * (BHN * DH) + h * DH + c4);
            q.x *= QK_SCALE; q.y *= QK_SCALE; q.z *= QK_SCALE; q.w *= QK_SCALE;
            uint32_t* dh = reinterpret_cast<uint32_t*>(sQh + hidx);
            uint32_t* dl = reinterpret_cast<uint32_t*>(sQl + hidx);
            dh[0] = pack_hi(q.x, q.y); dh[1] = pack_hi(q.z, q.w);
            dl[0] = pack_lo(q.x, q.y); dl[1] = pack_lo(q.z, q.w);

            float4 kk = *reinterpret_cast<const float4*>(
                K + (size_t)(sb + r) * (BHN * DH) + h * DH + c4);
            uint32_t* eh = reinterpret_cast<uint32_t*>(sKh + hidx);
            uint32_t* el = reinterpret_cast<uint32_t*>(sKl + hidx);
            eh[0] = pack_hi(kk.x, kk.y); eh[1] = pack_hi(kk.z, kk.w);
            el[0] = pack_lo(kk.x, kk.y); el[1] = pack_lo(kk.z, kk.w);
        }
        __syncthreads();

        float acc[2][8][4];
#pragma unroll
        for (int i = 0; i < 2; ++i)
#pragma unroll
            for (int j = 0; j < 8; ++j)
#pragma unroll
                for (int q = 0; q < 4; ++q) acc[i][j][q] = 0.0f;

#pragma unroll
        for (int ks = 0; ks < 4; ++ks) {
            const int k0 = ks * 16;
            uint32_t ah[2][4], al[2][4], bh[4][4], bl[4][4];
#pragma unroll
            for (int mi = 0; mi < 2; ++mi) {
                uint32_t off = ((wt + mi * 16 + a_row) * STR + k0 + a_co8) * 2;
                ldmx4(ah[mi], bQh + off);
                ldmx4(al[mi], bQl + off);
            }
#pragma unroll
            for (int p = 0; p < 4; ++p) {
                uint32_t off = ((ws + p * 16 + b_row) * STR + k0 + b_co8) * 2;
                ldmx4(bh[p], bKh + off);
                ldmx4(bl[p], bKl + off);
            }
#pragma unroll
            for (int mi = 0; mi < 2; ++mi)
#pragma unroll
                for (int ni = 0; ni < 8; ++ni) {
                    const uint32_t* Bh = &bh[ni >> 1][(ni & 1) * 2];
                    const uint32_t* Bl = &bl[ni >> 1][(ni & 1) * 2];
                    mma_bf16(acc[mi][ni], ah[mi], Bh);
                    mma_bf16(acc[mi][ni], ah[mi], Bl);
                    mma_bf16(acc[mi][ni], al[mi], Bh);
                }
        }

        // Epilogue: mask bits -> exp -> store; per-row partial sums.
        float rs[4] = {0.0f, 0.0f, 0.0f, 0.0f};
#pragma unroll
        for (int mi = 0; mi < 2; ++mi) {
#pragma unroll
            for (int ni = 0; ni < 8; ++ni) {
                int t0 = tb + wt + mi * 16 + (lane >> 2);
                int s  = sb + ws + ni * 8 + (lane & 3) * 2;
                int p  = (mi * 8 + ni) * 4;

                float2 o0;
                o0.x = (mb >> p)       & 1 ? 0.0f : __expf(acc[mi][ni][0]);
                o0.y = (mb >> (p + 1)) & 1 ? 0.0f : __expf(acc[mi][ni][1]);
                *reinterpret_cast<float2*>(W + ((size_t)h * TGT + t0) * SRC + s) = o0;
                rs[mi * 2] += o0.x + o0.y;

                float2 o1;
                o1.x = (mb >> (p + 2)) & 1 ? 0.0f : __expf(acc[mi][ni][2]);
                o1.y = (mb >> (p + 3)) & 1 ? 0.0f : __expf(acc[mi][ni][3]);
                *reinterpret_cast<float2*>(W + ((size_t)h * TGT + t0 + 8) * SRC + s) = o1;
                rs[mi * 2 + 1] += o1.x + o1.y;
            }
        }

#pragma unroll
        for (int o = 1; o <= 2; o <<= 1) {
#pragma unroll
            for (int i = 0; i < 4; ++i)
                rs[i] += __shfl_xor_sync(0xffffffffu, rs[i], o);
        }
        if ((lane & 3) == 0) {
            const int slot = blockIdx.x * 2 + (wid >> 2);
            const size_t rb = (size_t)h * TGT + tb + wt + (lane >> 2);
            LSUM[(rb +  0) * 32 + slot] = rs[0];
            LSUM[(rb +  8) * 32 + slot] = rs[1];
            LSUM[(rb + 16) * 32 + slot] = rs[2];
            LSUM[(rb + 24) * 32 + slot] = rs[3];
        }
    }
}

// ---------------------------------------------------------------------------
// Kernel C: normalizes W in place (final softmax output) AND computes
// out[t,h,d] = sum_s Wn[h,t,s] * V[s,h,d]   (bf16-split HMMA)
// Block 256 thr, tile 128t x 64d; 64 s-chunks of 32.
// Register prefetch + DOUBLE-BUFFERED smem: one __syncthreads per chunk;
// storeChunk(c+1) targets the opposite buffer of in-flight MMAs.
// Warps 4(t) x 2(d); warp tile 32x32.
// ---------------------------------------------------------------------------
#define PV_BUF_HALFS (2 * 128 * PSTR + 2 * 64 * PSTR)      // 15360 halfs
#define PV_SMEM_BYTES (2 * PV_BUF_HALFS * 2)               // 61440 B

__global__ __launch_bounds__(256, 2) void pv_tc_kernel(
    float* __restrict__ W, const float* __restrict__ V,
    float* __restrict__ Out)
{
    extern __shared__ char smem[];
    __shared__ float sInv[128];
    __nv_bfloat16* sBase = reinterpret_cast<__nv_bfloat16*>(smem);

    const int tid = threadIdx.x;
    const int lane = tid & 31, wid = tid >> 5;
    const int h  = blockIdx.y;
    const int tb = blockIdx.x * 128;
    const int wt = (wid & 3) * 32;
    const int wd = (wid >> 2) * 32;

    // Row normalizers from deterministic partial sums.
    if (tid < 128) {
        const float4* b4 = reinterpret_cast<const float4*>(
            LSUM + ((size_t)h * TGT + tb + tid) * 32);
        float s = 0.0f;
#pragma unroll
        for (int j = 0; j < 8; ++j) {
            float4 v = b4[j];
            s += v.x + v.y + v.z + v.w;
        }
        sInv[tid] = 1.0f / s;
    }
    __syncthreads();

    // Per-thread load/store geometry.
    const int w_r  = tid >> 3;          // 0..31 -> rows (x4 over k)
    const int w_c4 = (tid & 7) << 2;    // 0..28
    const int v_s2 = tid & 15;          // s-pair 0..15
    const int v_d4 = (tid >> 4) << 2;   // 0..60

    float4 wreg[4];
    float4 vreg[2];

    auto loadChunk = [&](int c) {
        const int s0 = c * 32;
#pragma unroll
        for (int k = 0; k < 4; ++k) {
            int r = w_r + k * 32;
            wreg[k] = *reinterpret_cast<const float4*>(
                W + ((size_t)h * TGT + tb + r) * SRC + s0 + w_c4);
        }
        vreg[0] = *reinterpret_cast<const float4*>(
            V + (size_t)(s0 + v_s2 * 2) * (BHN * DH) + h * DH + v_d4);
        vreg[1] = *reinterpret_cast<const float4*>(
            V + (size_t)(s0 + v_s2 * 2 + 1) * (BHN * DH) + h * DH + v_d4);
    };

    auto storeChunk = [&](int c, int b) {
        __nv_bfloat16* sPh = sBase + b * PV_BUF_HALFS;
        __nv_bfloat16* sPl = sPh + 128 * PSTR;
        __nv_bfloat16* sVh = sPl + 128 * PSTR;
        __nv_bfloat16* sVl = sVh + 64 * PSTR;
        const int s0 = c * 32;
#pragma unroll
        for (int k = 0; k < 4; ++k) {
            int r = w_r + k * 32;
            float4 p = wreg[k];
            const float inv = sInv[r];
            p.x *= inv; p.y *= inv; p.z *= inv; p.w *= inv;
            *reinterpret_cast<float4*>(
                W + ((size_t)h * TGT + tb + r) * SRC + s0 + w_c4) = p;  // final softmax
            uint32_t* dh = reinterpret_cast<uint32_t*>(sPh + r * PSTR + w_c4);
            uint32_t* dl = reinterpret_cast<uint32_t*>(sPl + r * PSTR + w_c4);
            dh[0] = pack_hi(p.x, p.y); dh[1] = pack_hi(p.z, p.w);
            dl[0] = pack_lo(p.x, p.y); dl[1] = pack_lo(p.z, p.w);
        }
        float av[4] = {vreg[0].x, vreg[0].y, vreg[0].z, vreg[0].w};
        float bv[4] = {vreg[1].x, vreg[1].y, vreg[1].z, vreg[1].w};
#pragma unroll
        for (int j = 0; j < 4; ++j) {
            int idx = (v_d4 + j) * PSTR + v_s2 * 2;
            *reinterpret_cast<uint32_t*>(sVh + idx) = pack_hi(av[j], bv[j]);
            *reinterpret_cast<uint32_t*>(sVl + idx) = pack_lo(av[j], bv[j]);
        }
    };

    const int a_row = (lane & 15);
    const int a_co8 = (lane >> 4) << 3;
    const int b_row = (lane & 7) + ((lane & 16) >> 1);
    const int b_co8 = (lane & 8);

    float acc[2][4][4];
#pragma unroll
    for (int i = 0; i < 2; ++i)
#pragma unroll
        for (int j = 0; j < 4; ++j)
#pragma unroll
            for (int q = 0; q < 4; ++q) acc[i][j][q] = 0.0f;

    loadChunk(0);
    storeChunk(0, 0);
    __syncthreads();

#pragma unroll 1
    for (int c = 0; c < SRC / 32; ++c) {
        const bool more = (c + 1) < SRC / 32;
        if (more) loadChunk(c + 1);   // LDGs in flight during MMA phase

        const uint32_t bB = smem_to_u32(sBase + (c & 1) * PV_BUF_HALFS);
        const uint32_t bPh = bB;
        const uint32_t bPl = bB + 128 * PSTR * 2;
        const uint32_t bVh = bB + 2 * 128 * PSTR * 2;
        const uint32_t bVl = bB + (2 * 128 + 64) * PSTR * 2;

#pragma unroll
        for (int ks = 0; ks < 2; ++ks) {
            const int k0 = ks * 16;
            uint32_t ah[2][4], al[2][4], bh[2][4], bl[2][4];
#pragma unroll
            for (int mi = 0; mi < 2; ++mi) {
                uint32_t off = ((wt + mi * 16 + a_row) * PSTR + k0 + a_co8) * 2;
                ldmx4(ah[mi], bPh + off);
                ldmx4(al[mi], bPl + off);
            }
#pragma unroll
            for (int p = 0; p < 2; ++p) {
                uint32_t off = ((wd + p * 16 + b_row) * PSTR + k0 + b_co8) * 2;
                ldmx4(bh[p], bVh + off);
                ldmx4(bl[p], bVl + off);
            }
#pragma unroll
            for (int mi = 0; mi < 2; ++mi)
#pragma unroll
                for (int ni = 0; ni < 4; ++ni) {
                    const uint32_t* Bh = &bh[ni >> 1][(ni & 1) * 2];
                    const uint32_t* Bl = &bl[ni >> 1][(ni & 1) * 2];
                    mma_bf16(acc[mi][ni], ah[mi], Bh);
                    mma_bf16(acc[mi][ni], ah[mi], Bl);
                    mma_bf16(acc[mi][ni], al[mi], Bh);
                }
        }

        if (more) storeChunk(c + 1, (c + 1) & 1);   // opposite buffer: no hazard
        __syncthreads();
    }

    // Epilogue: Out[t, h, d].
#pragma unroll
    for (int mi = 0; mi < 2; ++mi) {
#pragma unroll
        for (int ni = 0; ni < 4; ++ni) {
            int t0 = tb + wt + mi * 16 + (lane >> 2);
            int d  = wd + ni * 8 + (lane & 3) * 2;
            float2 o0 = make_float2(acc[mi][ni][0], acc[mi][ni][1]);
            float2 o1 = make_float2(acc[mi][ni][2], acc[mi][ni][3]);
            *reinterpret_cast<float2*>(Out + (size_t)t0 * (BHN * DH) + h * DH + d) = o0;
            *reinterpret_cast<float2*>(Out + (size_t)(t0 + 8) * (BHN * DH) + h * DH + d) = o1;
        }
    }
}

// ---------------------------------------------------------------------------
// Launch: out buffer = [out (2048*16*64) | w (16*2048*2048)] fp32.
// ---------------------------------------------------------------------------
extern "C" void kernel_launch(void* const* d_in, const int* in_sizes, int n_in,
                              void* d_out, int out_size)
{
    const float* Q = (const float*)d_in[0];
    const float* K = (const float*)d_in[1];
    const float* V = (const float*)d_in[2];
    const int*   M = (const int*)d_in[3];

    float* out = (float*)d_out;
    float* W   = out + (size_t)TGT * BHN * DH;

    cudaFuncSetAttribute(qk_tc_kernel,
                         cudaFuncAttributeMaxDynamicSharedMemorySize, QK_SMEM_BYTES);
    cudaFuncSetAttribute(pv_tc_kernel,
                         cudaFuncAttributeMaxDynamicSharedMemorySize, PV_SMEM_BYTES);

    qk_tc_kernel<<<dim3(SRC / 128, TGT / 128, 2), 256, QK_SMEM_BYTES>>>(Q, K, M, W);
    pv_tc_kernel<<<dim3(TGT / 128, BHN), 256, PV_SMEM_BYTES>>>(W, V, out);
}

// round 16
// speedup vs baseline: 1.0663x; 1.0663x over previous
#include <cuda_runtime.h>
#include <cuda_bf16.h>
#include <cstdint>

#define TGT 2048
#define SRC 2048
#define BHN 16
#define DH  64
#define QK_SCALE 0.125f

#define STR 72    // QK smem stride (halfs): 144B rows, conflict-free ldmatrix
#define PSTR 40   // PV smem stride (halfs): 80B rows, conflict-free ldmatrix
#define QK_HLOOP 4

// Deterministic per-row exp-sum partials: [h][t][sblock*2 + swarp]
__device__ float LSUM[(size_t)BHN * TGT * 32];

// ---------------------------------------------------------------------------
// Helpers
// ---------------------------------------------------------------------------
__device__ __forceinline__ uint32_t smem_to_u32(const void* p) {
    uint32_t a;
    asm("{ .reg .u64 t; cvta.to.shared.u64 t, %1; cvt.u32.u64 %0, t; }"
        : "=r"(a) : "l"(p));
    return a;
}

__device__ __forceinline__ void ldmx4(uint32_t* r, uint32_t a) {
    asm volatile("ldmatrix.sync.aligned.m8n8.x4.shared.b16 {%0,%1,%2,%3}, [%4];"
                 : "=r"(r[0]), "=r"(r[1]), "=r"(r[2]), "=r"(r[3]) : "r"(a));
}

__device__ __forceinline__ void mma_bf16(float* c, const uint32_t* a, const uint32_t* b) {
    asm volatile(
        "mma.sync.aligned.m16n8k16.row.col.f32.bf16.bf16.f32 "
        "{%0,%1,%2,%3}, {%4,%5,%6,%7}, {%8,%9}, {%0,%1,%2,%3};"
        : "+f"(c[0]), "+f"(c[1]), "+f"(c[2]), "+f"(c[3])
        : "r"(a[0]), "r"(a[1]), "r"(a[2]), "r"(a[3]), "r"(b[0]), "r"(b[1]));
}

__device__ __forceinline__ uint32_t pack_hi(float a, float b) {
    __nv_bfloat162 t = __floats2bfloat162_rn(a, b);
    return *reinterpret_cast<uint32_t*>(&t);
}
__device__ __forceinline__ float bf_hi(float x) {
    return __bfloat162float(__float2bfloat16_rn(x));
}
__device__ __forceinline__ uint32_t pack_lo(float a, float b) {
    __nv_bfloat162 t = __floats2bfloat162_rn(a - bf_hi(a), b - bf_hi(b));
    return *reinterpret_cast<uint32_t*>(&t);
}

// ---------------------------------------------------------------------------
// Kernel A: W[h,t,s] = mask ? 0 : exp((Q/8)·K), plus per-row partial sums.
// Block 256 thr, tile 128x128, loops over QK_HLOOP=4 heads (z selects group):
// grid 16x16x4 = 1024 blocks = 3.46 waves (r15's z=2 gave 1.7 waves -> tail).
// Mask bits packed into one uint64 register once, reused across 4 heads.
// Warps 4(t) x 2(s); warp tile 32x64 (1:4 ldm:MMA).
// exp without max-subtraction is safe: |logit| <~ 8 (unit-variance inputs).
// ---------------------------------------------------------------------------
#define QK_SMEM_BYTES (4 * 128 * STR * 2)   // Qhi, Qlo, Khi, Klo

__global__ __launch_bounds__(256, 2) void qk_tc_kernel(
    const float* __restrict__ Q, const float* __restrict__ K,
    const int* __restrict__ mask, float* __restrict__ W)
{
    extern __shared__ char smem[];
    __nv_bfloat16* sQh = reinterpret_cast<__nv_bfloat16*>(smem);
    __nv_bfloat16* sQl = sQh + 128 * STR;
    __nv_bfloat16* sKh = sQl + 128 * STR;
    __nv_bfloat16* sKl = sKh + 128 * STR;

    const int tid = threadIdx.x;
    const int lane = tid & 31, wid = tid >> 5;
    const int tb = blockIdx.y * 128;
    const int sb = blockIdx.x * 128;
    const int hbase = blockIdx.z * QK_HLOOP;
    const int wt = (wid & 3) * 32;
    const int ws = (wid >> 2) * 64;

    // Pack this thread's epilogue mask bits (h-invariant) once.
    uint64_t mb = 0;
#pragma unroll
    for (int mi = 0; mi < 2; ++mi) {
#pragma unroll
        for (int ni = 0; ni < 8; ++ni) {
            int t0 = tb + wt + mi * 16 + (lane >> 2);
            int s  = sb + ws + ni * 8 + (lane & 3) * 2;
            int2 m0 = *reinterpret_cast<const int2*>(mask + (size_t)t0 * SRC + s);
            int2 m1 = *reinterpret_cast<const int2*>(mask + (size_t)(t0 + 8) * SRC + s);
            int p = (mi * 8 + ni) * 4;
            mb |= (uint64_t)(m0.x ? 1u : 0u) << p;
            mb |= (uint64_t)(m0.y ? 1u : 0u) << (p + 1);
            mb |= (uint64_t)(m1.x ? 1u : 0u) << (p + 2);
            mb |= (uint64_t)(m1.y ? 1u : 0u) << (p + 3);
        }
    }

    const uint32_t bQh = smem_to_u32(sQh), bQl = smem_to_u32(sQl);
    const uint32_t bKh = smem_to_u32(sKh), bKl = smem_to_u32(sKl);

    const int a_row = (lane & 15);
    const int a_co8 = (lane >> 4) << 3;
    const int b_row = (lane & 7) + ((lane & 16) >> 1);
    const int b_co8 = (lane & 8);

#pragma unroll 1
    for (int hh = 0; hh < QK_HLOOP; ++hh) {
        const int h = hbase + hh;
        __syncthreads();   // prior iteration's ldmatrix reads complete

        // Convert Q (scaled) and K tiles to bf16 hi/lo.
#pragma unroll
        for (int k = 0; k < 8; ++k) {
            int i  = tid + k * 256;
            int r  = i >> 4;
            int c4 = (i & 15) << 2;
            int hidx = r * STR + c4;

            float4 q = *reinterpret_cast<const float4*>(
                Q + (size_t)(tb + r) * (BHN * DH) + h * DH + c4);
            q.x *= QK_SCALE; q.y *= QK_SCALE; q.z *= QK_SCALE; q.w *= QK_SCALE;
            uint32_t* dh = reinterpret_cast<uint32_t*>(sQh + hidx);
            uint32_t* dl = reinterpret_cast<uint32_t*>(sQl + hidx);
            dh[0] = pack_hi(q.x, q.y); dh[1] = pack_hi(q.z, q.w);
            dl[0] = pack_lo(q.x, q.y); dl[1] = pack_lo(q.z, q.w);

            float4 kk = *reinterpret_cast<const float4*>(
                K + (size_t)(sb + r) * (BHN * DH) + h * DH + c4);
            uint32_t* eh = reinterpret_cast<uint32_t*>(sKh + hidx);
            uint32_t* el = reinterpret_cast<uint32_t*>(sKl + hidx);
            eh[0] = pack_hi(kk.x, kk.y); eh[1] = pack_hi(kk.z, kk.w);
            el[0] = pack_lo(kk.x, kk.y); el[1] = pack_lo(kk.z, kk.w);
        }
        __syncthreads();

        float acc[2][8][4];
#pragma unroll
        for (int i = 0; i < 2; ++i)
#pragma unroll
            for (int j = 0; j < 8; ++j)
#pragma unroll
                for (int q = 0; q < 4; ++q) acc[i][j][q] = 0.0f;

#pragma unroll
        for (int ks = 0; ks < 4; ++ks) {
            const int k0 = ks * 16;
            uint32_t ah[2][4], al[2][4], bh[4][4], bl[4][4];
#pragma unroll
            for (int mi = 0; mi < 2; ++mi) {
                uint32_t off = ((wt + mi * 16 + a_row) * STR + k0 + a_co8) * 2;
                ldmx4(ah[mi], bQh + off);
                ldmx4(al[mi], bQl + off);
            }
#pragma unroll
            for (int p = 0; p < 4; ++p) {
                uint32_t off = ((ws + p * 16 + b_row) * STR + k0 + b_co8) * 2;
                ldmx4(bh[p], bKh + off);
                ldmx4(bl[p], bKl + off);
            }
#pragma unroll
            for (int mi = 0; mi < 2; ++mi)
#pragma unroll
                for (int ni = 0; ni < 8; ++ni) {
                    const uint32_t* Bh = &bh[ni >> 1][(ni & 1) * 2];
                    const uint32_t* Bl = &bl[ni >> 1][(ni & 1) * 2];
                    mma_bf16(acc[mi][ni], ah[mi], Bh);
                    mma_bf16(acc[mi][ni], ah[mi], Bl);
                    mma_bf16(acc[mi][ni], al[mi], Bh);
                }
        }

        // Epilogue: mask bits -> exp -> streaming store; per-row partial sums.
        float rs[4] = {0.0f, 0.0f, 0.0f, 0.0f};
#pragma unroll
        for (int mi = 0; mi < 2; ++mi) {
#pragma unroll
            for (int ni = 0; ni < 8; ++ni) {
                int t0 = tb + wt + mi * 16 + (lane >> 2);
                int s  = sb + ws + ni * 8 + (lane & 3) * 2;
                int p  = (mi * 8 + ni) * 4;

                float2 o0;
                o0.x = (mb >> p)       & 1 ? 0.0f : __expf(acc[mi][ni][0]);
                o0.y = (mb >> (p + 1)) & 1 ? 0.0f : __expf(acc[mi][ni][1]);
                __stcs(reinterpret_cast<float2*>(
                    W + ((size_t)h * TGT + t0) * SRC + s), o0);
                rs[mi * 2] += o0.x + o0.y;

                float2 o1;
                o1.x = (mb >> (p + 2)) & 1 ? 0.0f : __expf(acc[mi][ni][2]);
                o1.y = (mb >> (p + 3)) & 1 ? 0.0f : __expf(acc[mi][ni][3]);
                __stcs(reinterpret_cast<float2*>(
                    W + ((size_t)h * TGT + t0 + 8) * SRC + s), o1);
                rs[mi * 2 + 1] += o1.x + o1.y;
            }
        }

#pragma unroll
        for (int o = 1; o <= 2; o <<= 1) {
#pragma unroll
            for (int i = 0; i < 4; ++i)
                rs[i] += __shfl_xor_sync(0xffffffffu, rs[i], o);
        }
        if ((lane & 3) == 0) {
            const int slot = blockIdx.x * 2 + (wid >> 2);
            const size_t rb = (size_t)h * TGT + tb + wt + (lane >> 2);
            LSUM[(rb +  0) * 32 + slot] = rs[0];
            LSUM[(rb +  8) * 32 + slot] = rs[1];
            LSUM[(rb + 16) * 32 + slot] = rs[2];
            LSUM[(rb + 24) * 32 + slot] = rs[3];
        }
    }
}

// ---------------------------------------------------------------------------
// Kernel C: normalizes W in place (final softmax output) AND computes
// out[t,h,d] = sum_s Wn[h,t,s] * V[s,h,d]   (bf16-split HMMA)
// Block 256 thr, tile 128t x 64d; 64 s-chunks of 32.
// Register prefetch + double-buffered smem: one __syncthreads per chunk.
// W accessed with streaming hints (.cs): read-once / write-never-reread.
// Warps 4(t) x 2(d); warp tile 32x32.
// ---------------------------------------------------------------------------
#define PV_BUF_HALFS (2 * 128 * PSTR + 2 * 64 * PSTR)      // 15360 halfs
#define PV_SMEM_BYTES (2 * PV_BUF_HALFS * 2)               // 61440 B

__global__ __launch_bounds__(256, 2) void pv_tc_kernel(
    float* __restrict__ W, const float* __restrict__ V,
    float* __restrict__ Out)
{
    extern __shared__ char smem[];
    __shared__ float sInv[128];
    __nv_bfloat16* sBase = reinterpret_cast<__nv_bfloat16*>(smem);

    const int tid = threadIdx.x;
    const int lane = tid & 31, wid = tid >> 5;
    const int h  = blockIdx.y;
    const int tb = blockIdx.x * 128;
    const int wt = (wid & 3) * 32;
    const int wd = (wid >> 2) * 32;

    // Row normalizers from deterministic partial sums.
    if (tid < 128) {
        const float4* b4 = reinterpret_cast<const float4*>(
            LSUM + ((size_t)h * TGT + tb + tid) * 32);
        float s = 0.0f;
#pragma unroll
        for (int j = 0; j < 8; ++j) {
            float4 v = b4[j];
            s += v.x + v.y + v.z + v.w;
        }
        sInv[tid] = 1.0f / s;
    }
    __syncthreads();

    // Per-thread load/store geometry.
    const int w_r  = tid >> 3;          // 0..31 -> rows (x4 over k)
    const int w_c4 = (tid & 7) << 2;    // 0..28
    const int v_s2 = tid & 15;          // s-pair 0..15
    const int v_d4 = (tid >> 4) << 2;   // 0..60

    float4 wreg[4];
    float4 vreg[2];

    auto loadChunk = [&](int c) {
        const int s0 = c * 32;
#pragma unroll
        for (int k = 0; k < 4; ++k) {
            int r = w_r + k * 32;
            wreg[k] = __ldcs(reinterpret_cast<const float4*>(
                W + ((size_t)h * TGT + tb + r) * SRC + s0 + w_c4));
        }
        vreg[0] = *reinterpret_cast<const float4*>(
            V + (size_t)(s0 + v_s2 * 2) * (BHN * DH) + h * DH + v_d4);
        vreg[1] = *reinterpret_cast<const float4*>(
            V + (size_t)(s0 + v_s2 * 2 + 1) * (BHN * DH) + h * DH + v_d4);
    };

    auto storeChunk = [&](int c, int b) {
        __nv_bfloat16* sPh = sBase + b * PV_BUF_HALFS;
        __nv_bfloat16* sPl = sPh + 128 * PSTR;
        __nv_bfloat16* sVh = sPl + 128 * PSTR;
        __nv_bfloat16* sVl = sVh + 64 * PSTR;
        const int s0 = c * 32;
#pragma unroll
        for (int k = 0; k < 4; ++k) {
            int r = w_r + k * 32;
            float4 p = wreg[k];
            const float inv = sInv[r];
            p.x *= inv; p.y *= inv; p.z *= inv; p.w *= inv;
            __stcs(reinterpret_cast<float4*>(
                W + ((size_t)h * TGT + tb + r) * SRC + s0 + w_c4), p);  // final softmax
            uint32_t* dh = reinterpret_cast<uint32_t*>(sPh + r * PSTR + w_c4);
            uint32_t* dl = reinterpret_cast<uint32_t*>(sPl + r * PSTR + w_c4);
            dh[0] = pack_hi(p.x, p.y); dh[1] = pack_hi(p.z, p.w);
            dl[0] = pack_lo(p.x, p.y); dl[1] = pack_lo(p.z, p.w);
        }
        float av[4] = {vreg[0].x, vreg[0].y, vreg[0].z, vreg[0].w};
        float bv[4] = {vreg[1].x, vreg[1].y, vreg[1].z, vreg[1].w};
#pragma unroll
        for (int j = 0; j < 4; ++j) {
            int idx = (v_d4 + j) * PSTR + v_s2 * 2;
            *reinterpret_cast<uint32_t*>(sVh + idx) = pack_hi(av[j], bv[j]);
            *reinterpret_cast<uint32_t*>(sVl + idx) = pack_lo(av[j], bv[j]);
        }
    };

    const int a_row = (lane & 15);
    const int a_co8 = (lane >> 4) << 3;
    const int b_row = (lane & 7) + ((lane & 16) >> 1);
    const int b_co8 = (lane & 8);

    float acc[2][4][4];
#pragma unroll
    for (int i = 0; i < 2; ++i)
#pragma unroll
        for (int j = 0; j < 4; ++j)
#pragma unroll
            for (int q = 0; q < 4; ++q) acc[i][j][q] = 0.0f;

    loadChunk(0);
    storeChunk(0, 0);
    __syncthreads();

#pragma unroll 1
    for (int c = 0; c < SRC / 32; ++c) {
        const bool more = (c + 1) < SRC / 32;
        if (more) loadChunk(c + 1);   // LDGs in flight during MMA phase

        const uint32_t bB = smem_to_u32(sBase + (c & 1) * PV_BUF_HALFS);
        const uint32_t bPh = bB;
        const uint32_t bPl = bB + 128 * PSTR * 2;
        const uint32_t bVh = bB + 2 * 128 * PSTR * 2;
        const uint32_t bVl = bB + (2 * 128 + 64) * PSTR * 2;

#pragma unroll
        for (int ks = 0; ks < 2; ++ks) {
            const int k0 = ks * 16;
            uint32_t ah[2][4], al[2][4], bh[2][4], bl[2][4];
#pragma unroll
            for (int mi = 0; mi < 2; ++mi) {
                uint32_t off = ((wt + mi * 16 + a_row) * PSTR + k0 + a_co8) * 2;
                ldmx4(ah[mi], bPh + off);
                ldmx4(al[mi], bPl + off);
            }
#pragma unroll
            for (int p = 0; p < 2; ++p) {
                uint32_t off = ((wd + p * 16 + b_row) * PSTR + k0 + b_co8) * 2;
                ldmx4(bh[p], bVh + off);
                ldmx4(bl[p], bVl + off);
            }
#pragma unroll
            for (int mi = 0; mi < 2; ++mi)
#pragma unroll
                for (int ni = 0; ni < 4; ++ni) {
                    const uint32_t* Bh = &bh[ni >> 1][(ni & 1) * 2];
                    const uint32_t* Bl = &bl[ni >> 1][(ni & 1) * 2];
                    mma_bf16(acc[mi][ni], ah[mi], Bh);
                    mma_bf16(acc[mi][ni], ah[mi], Bl);
                    mma_bf16(acc[mi][ni], al[mi], Bh);
                }
        }

        if (more) storeChunk(c + 1, (c + 1) & 1);   // opposite buffer: no hazard
        __syncthreads();
    }

    // Epilogue: Out[t, h, d].
#pragma unroll
    for (int mi = 0; mi < 2; ++mi) {
#pragma unroll
        for (int ni = 0; ni < 4; ++ni) {
            int t0 = tb + wt + mi * 16 + (lane >> 2);
            int d  = wd + ni * 8 + (lane & 3) * 2;
            float2 o0 = make_float2(acc[mi][ni][0], acc[mi][ni][1]);
            float2 o1 = make_float2(acc[mi][ni][2], acc[mi][ni][3]);
            *reinterpret_cast<float2*>(Out + (size_t)t0 * (BHN * DH) + h * DH + d) = o0;
            *reinterpret_cast<float2*>(Out + (size_t)(t0 + 8) * (BHN * DH) + h * DH + d) = o1;
        }
    }
}

// ---------------------------------------------------------------------------
// Launch: out buffer = [out (2048*16*64) | w (16*2048*2048)] fp32.
// ---------------------------------------------------------------------------
extern "C" void kernel_launch(void* const* d_in, const int* in_sizes, int n_in,
                              void* d_out, int out_size)
{
    const float* Q = (const float*)d_in[0];
    const float* K = (const float*)d_in[1];
    const float* V = (const float*)d_in[2];
    const int*   M = (const int*)d_in[3];

    float* out = (float*)d_out;
    float* W   = out + (size_t)TGT * BHN * DH;

    cudaFuncSetAttribute(qk_tc_kernel,
                         cudaFuncAttributeMaxDynamicSharedMemorySize, QK_SMEM_BYTES);
    cudaFuncSetAttribute(pv_tc_kernel,
                         cudaFuncAttributeMaxDynamicSharedMemorySize, PV_SMEM_BYTES);

    qk_tc_kernel<<<dim3(SRC / 128, TGT / 128, BHN / QK_HLOOP), 256, QK_SMEM_BYTES>>>(Q, K, M, W);
    pv_tc_kernel<<<dim3(TGT / 128, BHN), 256, PV_SMEM_BYTES>>>(W, V, out);
}

// round 17
// speedup vs baseline: 1.1318x; 1.0614x over previous
#include <cuda_runtime.h>
#include <cuda_bf16.h>
#include <cstdint>

#define TGT 2048
#define SRC 2048
#define BHN 16
#define DH  64
#define QK_SCALE 0.125f

#define STR 72    // QK smem stride (halfs): 144B rows, conflict-free ldmatrix
#define PSTR 40   // PV smem stride (halfs): 80B rows, conflict-free ldmatrix

// Deterministic per-row exp-sum partials: [h][t][sblock*2 + swarp]
__device__ float LSUM[(size_t)BHN * TGT * 32];

// ---------------------------------------------------------------------------
// Helpers
// ---------------------------------------------------------------------------
__device__ __forceinline__ uint32_t smem_to_u32(const void* p) {
    uint32_t a;
    asm("{ .reg .u64 t; cvta.to.shared.u64 t, %1; cvt.u32.u64 %0, t; }"
        : "=r"(a) : "l"(p));
    return a;
}

__device__ __forceinline__ void ldmx4(uint32_t* r, uint32_t a) {
    asm volatile("ldmatrix.sync.aligned.m8n8.x4.shared.b16 {%0,%1,%2,%3}, [%4];"
                 : "=r"(r[0]), "=r"(r[1]), "=r"(r[2]), "=r"(r[3]) : "r"(a));
}

__device__ __forceinline__ void mma_bf16(float* c, const uint32_t* a, const uint32_t* b) {
    asm volatile(
        "mma.sync.aligned.m16n8k16.row.col.f32.bf16.bf16.f32 "
        "{%0,%1,%2,%3}, {%4,%5,%6,%7}, {%8,%9}, {%0,%1,%2,%3};"
        : "+f"(c[0]), "+f"(c[1]), "+f"(c[2]), "+f"(c[3])
        : "r"(a[0]), "r"(a[1]), "r"(a[2]), "r"(a[3]), "r"(b[0]), "r"(b[1]));
}

__device__ __forceinline__ uint32_t pack_hi(float a, float b) {
    __nv_bfloat162 t = __floats2bfloat162_rn(a, b);
    return *reinterpret_cast<uint32_t*>(&t);
}
__device__ __forceinline__ float bf_hi(float x) {
    return __bfloat162float(__float2bfloat16_rn(x));
}
__device__ __forceinline__ uint32_t pack_lo(float a, float b) {
    __nv_bfloat162 t = __floats2bfloat162_rn(a - bf_hi(a), b - bf_hi(b));
    return *reinterpret_cast<uint32_t*>(&t);
}

// ---------------------------------------------------------------------------
// Kernel A (r14 geometry — measured 125us): W[h,t,s] = mask ? 0 : exp((Q/8)·K),
// plus per-row partial sums. Block 256 thr, tile 128x128, grid (16,16,16).
// Warps 4(t) x 2(s); warp tile 32x64 (1:4 ldm:MMA).
// exp without max-subtraction is safe: |logit| <~ 8 (unit-variance inputs).
// ---------------------------------------------------------------------------
#define QK_SMEM_BYTES (4 * 128 * STR * 2)   // Qhi, Qlo, Khi, Klo

__global__ __launch_bounds__(256, 2) void qk_tc_kernel(
    const float* __restrict__ Q, const float* __restrict__ K,
    const int* __restrict__ mask, float* __restrict__ W)
{
    extern __shared__ char smem[];
    __nv_bfloat16* sQh = reinterpret_cast<__nv_bfloat16*>(smem);
    __nv_bfloat16* sQl = sQh + 128 * STR;
    __nv_bfloat16* sKh = sQl + 128 * STR;
    __nv_bfloat16* sKl = sKh + 128 * STR;

    const int tid = threadIdx.x;
    const int h  = blockIdx.z;
    const int tb = blockIdx.y * 128;
    const int sb = blockIdx.x * 128;

#pragma unroll
    for (int k = 0; k < 8; ++k) {
        int i  = tid + k * 256;
        int r  = i >> 4;
        int c4 = (i & 15) << 2;
        int hidx = r * STR + c4;

        float4 q = *reinterpret_cast<const float4*>(
            Q + (size_t)(tb + r) * (BHN * DH) + h * DH + c4);
        q.x *= QK_SCALE; q.y *= QK_SCALE; q.z *= QK_SCALE; q.w *= QK_SCALE;
        uint32_t* dh = reinterpret_cast<uint32_t*>(sQh + hidx);
        uint32_t* dl = reinterpret_cast<uint32_t*>(sQl + hidx);
        dh[0] = pack_hi(q.x, q.y); dh[1] = pack_hi(q.z, q.w);
        dl[0] = pack_lo(q.x, q.y); dl[1] = pack_lo(q.z, q.w);

        float4 kk = *reinterpret_cast<const float4*>(
            K + (size_t)(sb + r) * (BHN * DH) + h * DH + c4);
        uint32_t* eh = reinterpret_cast<uint32_t*>(sKh + hidx);
        uint32_t* el = reinterpret_cast<uint32_t*>(sKl + hidx);
        eh[0] = pack_hi(kk.x, kk.y); eh[1] = pack_hi(kk.z, kk.w);
        el[0] = pack_lo(kk.x, kk.y); el[1] = pack_lo(kk.z, kk.w);
    }
    __syncthreads();

    const int lane = tid & 31, wid = tid >> 5;
    const int wt = (wid & 3) * 32;
    const int ws = (wid >> 2) * 64;

    const uint32_t bQh = smem_to_u32(sQh), bQl = smem_to_u32(sQl);
    const uint32_t bKh = smem_to_u32(sKh), bKl = smem_to_u32(sKl);

    const int a_row = (lane & 15);
    const int a_co8 = (lane >> 4) << 3;
    const int b_row = (lane & 7) + ((lane & 16) >> 1);
    const int b_co8 = (lane & 8);

    float acc[2][8][4];
#pragma unroll
    for (int i = 0; i < 2; ++i)
#pragma unroll
        for (int j = 0; j < 8; ++j)
#pragma unroll
            for (int q = 0; q < 4; ++q) acc[i][j][q] = 0.0f;

#pragma unroll
    for (int ks = 0; ks < 4; ++ks) {
        const int k0 = ks * 16;
        uint32_t ah[2][4], al[2][4], bh[4][4], bl[4][4];
#pragma unroll
        for (int mi = 0; mi < 2; ++mi) {
            uint32_t off = ((wt + mi * 16 + a_row) * STR + k0 + a_co8) * 2;
            ldmx4(ah[mi], bQh + off);
            ldmx4(al[mi], bQl + off);
        }
#pragma unroll
        for (int p = 0; p < 4; ++p) {
            uint32_t off = ((ws + p * 16 + b_row) * STR + k0 + b_co8) * 2;
            ldmx4(bh[p], bKh + off);
            ldmx4(bl[p], bKl + off);
        }
#pragma unroll
        for (int mi = 0; mi < 2; ++mi)
#pragma unroll
            for (int ni = 0; ni < 8; ++ni) {
                const uint32_t* Bh = &bh[ni >> 1][(ni & 1) * 2];
                const uint32_t* Bl = &bl[ni >> 1][(ni & 1) * 2];
                mma_bf16(acc[mi][ni], ah[mi], Bh);
                mma_bf16(acc[mi][ni], ah[mi], Bl);
                mma_bf16(acc[mi][ni], al[mi], Bh);
            }
    }

    // Epilogue: mask -> exp -> store unnormalized weights; per-row partial sums.
    float rs[4] = {0.0f, 0.0f, 0.0f, 0.0f};
#pragma unroll
    for (int mi = 0; mi < 2; ++mi) {
#pragma unroll
        for (int ni = 0; ni < 8; ++ni) {
            int t0 = tb + wt + mi * 16 + (lane >> 2);
            int s  = sb + ws + ni * 8 + (lane & 3) * 2;

            int2 m0 = *reinterpret_cast<const int2*>(mask + (size_t)t0 * SRC + s);
            float2 o0;
            o0.x = m0.x ? 0.0f : __expf(acc[mi][ni][0]);
            o0.y = m0.y ? 0.0f : __expf(acc[mi][ni][1]);
            *reinterpret_cast<float2*>(W + ((size_t)h * TGT + t0) * SRC + s) = o0;
            rs[mi * 2] += o0.x + o0.y;

            int t1 = t0 + 8;
            int2 m1 = *reinterpret_cast<const int2*>(mask + (size_t)t1 * SRC + s);
            float2 o1;
            o1.x = m1.x ? 0.0f : __expf(acc[mi][ni][2]);
            o1.y = m1.y ? 0.0f : __expf(acc[mi][ni][3]);
            *reinterpret_cast<float2*>(W + ((size_t)h * TGT + t1) * SRC + s) = o1;
            rs[mi * 2 + 1] += o1.x + o1.y;
        }
    }

#pragma unroll
    for (int o = 1; o <= 2; o <<= 1) {
#pragma unroll
        for (int i = 0; i < 4; ++i)
            rs[i] += __shfl_xor_sync(0xffffffffu, rs[i], o);
    }
    if ((lane & 3) == 0) {
        const int slot = blockIdx.x * 2 + (wid >> 2);
        const size_t rb = (size_t)h * TGT + tb + wt + (lane >> 2);
        LSUM[(rb +  0) * 32 + slot] = rs[0];
        LSUM[(rb +  8) * 32 + slot] = rs[1];
        LSUM[(rb + 16) * 32 + slot] = rs[2];
        LSUM[(rb + 24) * 32 + slot] = rs[3];
    }
}

// ---------------------------------------------------------------------------
// Kernel C (r16 version — measured 138.6us): normalizes W in place (final
// softmax output) AND computes out[t,h,d] = sum_s Wn[h,t,s] * V[s,h,d].
// Block 256 thr, tile 128t x 64d; 64 s-chunks of 32.
// Register prefetch + double-buffered smem: one __syncthreads per chunk.
// W accessed with streaming hints (.cs). Warps 4(t) x 2(d); warp tile 32x32.
// ---------------------------------------------------------------------------
#define PV_BUF_HALFS (2 * 128 * PSTR + 2 * 64 * PSTR)      // 15360 halfs
#define PV_SMEM_BYTES (2 * PV_BUF_HALFS * 2)               // 61440 B

__global__ __launch_bounds__(256, 2) void pv_tc_kernel(
    float* __restrict__ W, const float* __restrict__ V,
    float* __restrict__ Out)
{
    extern __shared__ char smem[];
    __shared__ float sInv[128];
    __nv_bfloat16* sBase = reinterpret_cast<__nv_bfloat16*>(smem);

    const int tid = threadIdx.x;
    const int lane = tid & 31, wid = tid >> 5;
    const int h  = blockIdx.y;
    const int tb = blockIdx.x * 128;
    const int wt = (wid & 3) * 32;
    const int wd = (wid >> 2) * 32;

    // Row normalizers from deterministic partial sums.
    if (tid < 128) {
        const float4* b4 = reinterpret_cast<const float4*>(
            LSUM + ((size_t)h * TGT + tb + tid) * 32);
        float s = 0.0f;
#pragma unroll
        for (int j = 0; j < 8; ++j) {
            float4 v = b4[j];
            s += v.x + v.y + v.z + v.w;
        }
        sInv[tid] = 1.0f / s;
    }
    __syncthreads();

    // Per-thread load/store geometry.
    const int w_r  = tid >> 3;          // 0..31 -> rows (x4 over k)
    const int w_c4 = (tid & 7) << 2;    // 0..28
    const int v_s2 = tid & 15;          // s-pair 0..15
    const int v_d4 = (tid >> 4) << 2;   // 0..60

    float4 wreg[4];
    float4 vreg[2];

    auto loadChunk = [&](int c) {
        const int s0 = c * 32;
#pragma unroll
        for (int k = 0; k < 4; ++k) {
            int r = w_r + k * 32;
            wreg[k] = __ldcs(reinterpret_cast<const float4*>(
                W + ((size_t)h * TGT + tb + r) * SRC + s0 + w_c4));
        }
        vreg[0] = *reinterpret_cast<const float4*>(
            V + (size_t)(s0 + v_s2 * 2) * (BHN * DH) + h * DH + v_d4);
        vreg[1] = *reinterpret_cast<const float4*>(
            V + (size_t)(s0 + v_s2 * 2 + 1) * (BHN * DH) + h * DH + v_d4);
    };

    auto storeChunk = [&](int c, int b) {
        __nv_bfloat16* sPh = sBase + b * PV_BUF_HALFS;
        __nv_bfloat16* sPl = sPh + 128 * PSTR;
        __nv_bfloat16* sVh = sPl + 128 * PSTR;
        __nv_bfloat16* sVl = sVh + 64 * PSTR;
        const int s0 = c * 32;
#pragma unroll
        for (int k = 0; k < 4; ++k) {
            int r = w_r + k * 32;
            float4 p = wreg[k];
            const float inv = sInv[r];
            p.x *= inv; p.y *= inv; p.z *= inv; p.w *= inv;
            __stcs(reinterpret_cast<float4*>(
                W + ((size_t)h * TGT + tb + r) * SRC + s0 + w_c4), p);  // final softmax
            uint32_t* dh = reinterpret_cast<uint32_t*>(sPh + r * PSTR + w_c4);
            uint32_t* dl = reinterpret_cast<uint32_t*>(sPl + r * PSTR + w_c4);
            dh[0] = pack_hi(p.x, p.y); dh[1] = pack_hi(p.z, p.w);
            dl[0] = pack_lo(p.x, p.y); dl[1] = pack_lo(p.z, p.w);
        }
        float av[4] = {vreg[0].x, vreg[0].y, vreg[0].z, vreg[0].w};
        float bv[4] = {vreg[1].x, vreg[1].y, vreg[1].z, vreg[1].w};
#pragma unroll
        for (int j = 0; j < 4; ++j) {
            int idx = (v_d4 + j) * PSTR + v_s2 * 2;
            *reinterpret_cast<uint32_t*>(sVh + idx) = pack_hi(av[j], bv[j]);
            *reinterpret_cast<uint32_t*>(sVl + idx) = pack_lo(av[j], bv[j]);
        }
    };

    const int a_row = (lane & 15);
    const int a_co8 = (lane >> 4) << 3;
    const int b_row = (lane & 7) + ((lane & 16) >> 1);
    const int b_co8 = (lane & 8);

    float acc[2][4][4];
#pragma unroll
    for (int i = 0; i < 2; ++i)
#pragma unroll
        for (int j = 0; j < 4; ++j)
#pragma unroll
            for (int q = 0; q < 4; ++q) acc[i][j][q] = 0.0f;

    loadChunk(0);
    storeChunk(0, 0);
    __syncthreads();

#pragma unroll 1
    for (int c = 0; c < SRC / 32; ++c) {
        const bool more = (c + 1) < SRC / 32;
        if (more) loadChunk(c + 1);   // LDGs in flight during MMA phase

        const uint32_t bB = smem_to_u32(sBase + (c & 1) * PV_BUF_HALFS);
        const uint32_t bPh = bB;
        const uint32_t bPl = bB + 128 * PSTR * 2;
        const uint32_t bVh = bB + 2 * 128 * PSTR * 2;
        const uint32_t bVl = bB + (2 * 128 + 64) * PSTR * 2;

#pragma unroll
        for (int ks = 0; ks < 2; ++ks) {
            const int k0 = ks * 16;
            uint32_t ah[2][4], al[2][4], bh[2][4], bl[2][4];
#pragma unroll
            for (int mi = 0; mi < 2; ++mi) {
                uint32_t off = ((wt + mi * 16 + a_row) * PSTR + k0 + a_co8) * 2;
                ldmx4(ah[mi], bPh + off);
                ldmx4(al[mi], bPl + off);
            }
#pragma unroll
            for (int p = 0; p < 2; ++p) {
                uint32_t off = ((wd + p * 16 + b_row) * PSTR + k0 + b_co8) * 2;
                ldmx4(bh[p], bVh + off);
                ldmx4(bl[p], bVl + off);
            }
#pragma unroll
            for (int mi = 0; mi < 2; ++mi)
#pragma unroll
                for (int ni = 0; ni < 4; ++ni) {
                    const uint32_t* Bh = &bh[ni >> 1][(ni & 1) * 2];
                    const uint32_t* Bl = &bl[ni >> 1][(ni & 1) * 2];
                    mma_bf16(acc[mi][ni], ah[mi], Bh);
                    mma_bf16(acc[mi][ni], ah[mi], Bl);
                    mma_bf16(acc[mi][ni], al[mi], Bh);
                }
        }

        if (more) storeChunk(c + 1, (c + 1) & 1);   // opposite buffer: no hazard
        __syncthreads();
    }

    // Epilogue: Out[t, h, d].
#pragma unroll
    for (int mi = 0; mi < 2; ++mi) {
#pragma unroll
        for (int ni = 0; ni < 4; ++ni) {
            int t0 = tb + wt + mi * 16 + (lane >> 2);
            int d  = wd + ni * 8 + (lane & 3) * 2;
            float2 o0 = make_float2(acc[mi][ni][0], acc[mi][ni][1]);
            float2 o1 = make_float2(acc[mi][ni][2], acc[mi][ni][3]);
            *reinterpret_cast<float2*>(Out + (size_t)t0 * (BHN * DH) + h * DH + d) = o0;
            *reinterpret_cast<float2*>(Out + (size_t)(t0 + 8) * (BHN * DH) + h * DH + d) = o1;
        }
    }
}

// ---------------------------------------------------------------------------
// Launch: out buffer = [out (2048*16*64) | w (16*2048*2048)] fp32.
// ---------------------------------------------------------------------------
extern "C" void kernel_launch(void* const* d_in, const int* in_sizes, int n_in,
                              void* d_out, int out_size)
{
    const float* Q = (const float*)d_in[0];
    const float* K = (const float*)d_in[1];
    const float* V = (const float*)d_in[2];
    const int*   M = (const int*)d_in[3];

    float* out = (float*)d_out;
    float* W   = out + (size_t)TGT * BHN * DH;

    cudaFuncSetAttribute(qk_tc_kernel,
                         cudaFuncAttributeMaxDynamicSharedMemorySize, QK_SMEM_BYTES);
    cudaFuncSetAttribute(pv_tc_kernel,
                         cudaFuncAttributeMaxDynamicSharedMemorySize, PV_SMEM_BYTES);

    qk_tc_kernel<<<dim3(SRC / 128, TGT / 128, BHN), 256, QK_SMEM_BYTES>>>(Q, K, M, W);
    pv_tc_kernel<<<dim3(TGT / 128, BHN), 256, PV_SMEM_BYTES>>>(W, V, out);
}